// round 3
// baseline (speedup 1.0000x reference)
#include <cuda_runtime.h>
#include <cuda_bf16.h>
#include <math.h>

#define NN 50000
#define EE 800000
#define FIN 128
#define FOUT 128   // HEADS*C_OUT
#define HEADS 4
#define COUT 32
#define NEG_SLOPE 0.2f

// ---------------- scratch (device globals; no allocation) ----------------
__device__ __align__(16) float g_h[NN * FOUT];      // projected features
__device__ __align__(16) float g_asrc[NN * HEADS];  // per-node src logits
__device__ __align__(16) float g_adst[NN * HEADS];  // per-node dst logits
__device__ int g_deg[NN];
__device__ int g_off[NN];
__device__ int g_cur[NN];
__device__ int g_csr_src[EE];

// ---------------- tf32 helpers -------------------------------------------
__device__ __forceinline__ unsigned tf32_of(float f) {
    unsigned u;
    asm("cvt.rna.tf32.f32 %0, %1;" : "=r"(u) : "f"(f));
    return u;
}

__device__ __forceinline__ void mma_tf32(float* d, const unsigned* a, const unsigned* b) {
    asm("mma.sync.aligned.m16n8k8.row.col.f32.tf32.tf32.f32 "
        "{%0,%1,%2,%3},{%4,%5,%6,%7},{%8,%9},{%0,%1,%2,%3};"
        : "+f"(d[0]), "+f"(d[1]), "+f"(d[2]), "+f"(d[3])
        : "r"(a[0]), "r"(a[1]), "r"(a[2]), "r"(a[3]), "r"(b[0]), "r"(b[1]));
}

// ---------------- GEMM: h = x @ W  (tf32 tensor cores) --------------------
// Block: 64 rows x 128 cols, K=128 staged fully. 256 threads (8 warps).
// smem pre-permuted into fragment order:
//   A tile (mi,ki) m16k8: elem(ri,ci) -> lane=(ri&7)*4+(ci&3), reg=(ri>>3)+2*(ci>>2)
//   B tile (ki,ni) k8n8:  elem(kk,nn) -> lane=nn*4+(kk&3),     reg=kk>>2
#define GEMM_SMEM_U32 (8192 + 16384)   // A 32KB + B 64KB

__global__ void __launch_bounds__(256, 1) gemm_tf32_kernel(
        const float* __restrict__ x, const float* __restrict__ W) {
    extern __shared__ unsigned smem[];
    unsigned* sA = smem;          // 4 mi x 16 ki x 128
    unsigned* sB = smem + 8192;   // 16 ki x 16 ni x 64

    const int tid = threadIdx.x;
    const int rowBase = blockIdx.x * 64;

    // ---- stage A (x block) with permutation + tf32 convert
#pragma unroll
    for (int j = 0; j < 8; j++) {
        int idx4 = tid + j * 256;          // 0..2047 float4s
        int r64 = idx4 >> 5;               // 0..63
        int gk0 = (idx4 & 31) * 4;
        int gr = rowBase + r64;
        float4 v = (gr < NN) ? *(const float4*)&x[gr * FIN + gk0]
                             : make_float4(0.f, 0.f, 0.f, 0.f);
        int mi = r64 >> 4, ri = r64 & 15;
        float vals[4] = {v.x, v.y, v.z, v.w};
#pragma unroll
        for (int e = 0; e < 4; e++) {
            int gk = gk0 + e;
            int ki = gk >> 3, ci = gk & 7;
            int ln = (ri & 7) * 4 + (ci & 3);
            int rg = (ri >> 3) + 2 * (ci >> 2);
            sA[(mi * 16 + ki) * 128 + ln * 4 + rg] = tf32_of(vals[e]);
        }
    }
    // ---- stage B (W) with permutation + tf32 convert
#pragma unroll
    for (int j = 0; j < 16; j++) {
        int idx4 = tid + j * 256;          // 0..4095 float4s
        int kg = idx4 >> 5;                // 0..127
        int n0 = (idx4 & 31) * 4;
        float4 v = *(const float4*)&W[kg * FOUT + n0];
        int ki = kg >> 3, kk = kg & 7;
        float vals[4] = {v.x, v.y, v.z, v.w};
#pragma unroll
        for (int e = 0; e < 4; e++) {
            int n = n0 + e;
            int ni = n >> 3, nn = n & 7;
            int ln = nn * 4 + (kk & 3);
            int rg = kk >> 2;
            sB[(ki * 16 + ni) * 64 + ln * 2 + rg] = tf32_of(vals[e]);
        }
    }
    __syncthreads();

    // ---- compute
    const int wid = tid >> 5, lane = tid & 31;
    const int mi = wid & 3;
    const int nb = (wid >> 2) * 8;   // 8 n-tiles per warp

    float acc[8][4];
#pragma unroll
    for (int nj = 0; nj < 8; nj++)
#pragma unroll
        for (int c = 0; c < 4; c++) acc[nj][c] = 0.f;

#pragma unroll
    for (int ki = 0; ki < 16; ki++) {
        uint4 a4 = *(const uint4*)&sA[(mi * 16 + ki) * 128 + lane * 4];
        unsigned a[4] = {a4.x, a4.y, a4.z, a4.w};
#pragma unroll
        for (int nj = 0; nj < 8; nj++) {
            int ni = nb + nj;
            uint2 b2 = *(const uint2*)&sB[(ki * 16 + ni) * 64 + lane * 2];
            unsigned b[2] = {b2.x, b2.y};
            mma_tf32(acc[nj], a, b);
        }
    }

    // ---- epilogue: C layout c0,c1: row=lane>>2, cols 2*(lane&3)+{0,1}; c2,c3: row+8
    int r0 = rowBase + mi * 16 + (lane >> 2);
    int r1 = r0 + 8;
#pragma unroll
    for (int nj = 0; nj < 8; nj++) {
        int col0 = (nb + nj) * 8 + (lane & 3) * 2;
        if (r0 < NN) *(float2*)&g_h[r0 * FOUT + col0] = make_float2(acc[nj][0], acc[nj][1]);
        if (r1 < NN) *(float2*)&g_h[r1 * FOUT + col0] = make_float2(acc[nj][2], acc[nj][3]);
    }
}

// ---------------- per-node attention logits (warp per node) --------------
__global__ void a_kernel(const float* __restrict__ att_src, const float* __restrict__ att_dst) {
    int warp = (blockIdx.x * blockDim.x + threadIdx.x) >> 5;
    int lane = threadIdx.x & 31;
    if (warp >= NN) return;

    float4 hv = *(const float4*)&g_h[warp * FOUT + lane * 4];
    int head = lane >> 3;
    int off  = (lane & 7) * 4;
    const float* as = att_src + head * COUT + off;
    const float* ad = att_dst + head * COUT + off;
    float ps = hv.x * as[0] + hv.y * as[1] + hv.z * as[2] + hv.w * as[3];
    float pd = hv.x * ad[0] + hv.y * ad[1] + hv.z * ad[2] + hv.w * ad[3];
#pragma unroll
    for (int d = 4; d >= 1; d >>= 1) {
        ps += __shfl_xor_sync(0xffffffffu, ps, d);
        pd += __shfl_xor_sync(0xffffffffu, pd, d);
    }
    if ((lane & 7) == 0) {
        g_asrc[warp * HEADS + head] = ps;
        g_adst[warp * HEADS + head] = pd;
    }
}

// ---------------- CSR build ----------------------------------------------
__global__ void zero_deg_kernel() {
    int i = blockIdx.x * blockDim.x + threadIdx.x;
    if (i < NN) g_deg[i] = 0;
}

// edges are INT32 (JAX x64 disabled). layout: edges[0:EE]=src, edges[EE:2EE]=dst
__global__ void hist_kernel(const int* __restrict__ edges) {
    int e = blockIdx.x * blockDim.x + threadIdx.x;
    if (e < EE) {
        int dst = edges[EE + e];
        atomicAdd(&g_deg[dst], 1);
    }
}

__global__ void scan_kernel() {   // 1 block, 1024 threads, exclusive scan of g_deg
    __shared__ int ssum[1024];
    const int CH = (NN + 1023) / 1024;   // 49
    int t = threadIdx.x;
    int base = t * CH;

    int s = 0;
    for (int i = 0; i < CH; i++) {
        int idx = base + i;
        if (idx < NN) s += g_deg[idx];
    }
    ssum[t] = s;
    __syncthreads();
    for (int d = 1; d < 1024; d <<= 1) {
        int v = 0;
        if (t >= d) v = ssum[t - d];
        __syncthreads();
        ssum[t] += v;
        __syncthreads();
    }
    int prefix = (t > 0) ? ssum[t - 1] : 0;
    for (int i = 0; i < CH; i++) {
        int idx = base + i;
        if (idx < NN) {
            g_off[idx] = prefix;
            g_cur[idx] = prefix;
            prefix += g_deg[idx];
        }
    }
}

__global__ void scatter_kernel(const int* __restrict__ edges) {
    int e = blockIdx.x * blockDim.x + threadIdx.x;
    if (e < EE) {
        int src = edges[e];
        int dst = edges[EE + e];
        int pos = atomicAdd(&g_cur[dst], 1);
        g_csr_src[pos] = src;
    }
}

// ---------------- GAT aggregate: warp per dst node -----------------------
__global__ void gat_kernel(const float* __restrict__ bias, float* __restrict__ out) {
    int warp = (blockIdx.x * blockDim.x + threadIdx.x) >> 5;
    int lane = threadIdx.x & 31;
    if (warp >= NN) return;
    const int n = warp;

    const int start = g_off[n];
    const int deg   = g_deg[n];
    const int lane4 = lane * 4;
    float4 bv = *(const float4*)&bias[lane4];

    if (deg == 0) {
        *(float4*)&out[n * FOUT + lane4] = bv;
        return;
    }

    float4 ad4 = *(const float4*)&g_adst[n * HEADS];
    float adh[4] = {ad4.x, ad4.y, ad4.z, ad4.w};

    // ---- pass 1: online softmax stats per head, lane-parallel over edges
    float m[4] = {-1e30f, -1e30f, -1e30f, -1e30f};
    float s[4] = {0.f, 0.f, 0.f, 0.f};
    for (int i = lane; i < deg; i += 32) {
        int src = g_csr_src[start + i];
        float4 as4 = *(const float4*)&g_asrc[src * HEADS];
        float ev[4] = {as4.x + adh[0], as4.y + adh[1], as4.z + adh[2], as4.w + adh[3]};
#pragma unroll
        for (int h = 0; h < 4; h++) {
            float e = ev[h];
            e = (e > 0.f) ? e : NEG_SLOPE * e;
            float nm = fmaxf(m[h], e);
            s[h] = s[h] * __expf(m[h] - nm) + __expf(e - nm);
            m[h] = nm;
        }
    }
    // warp combine (safe with -1e30 sentinel: no inf-inf NaN)
#pragma unroll
    for (int h = 0; h < 4; h++) {
#pragma unroll
        for (int d = 16; d >= 1; d >>= 1) {
            float mo = __shfl_xor_sync(0xffffffffu, m[h], d);
            float so = __shfl_xor_sync(0xffffffffu, s[h], d);
            float nm = fmaxf(m[h], mo);
            s[h] = s[h] * __expf(m[h] - nm) + so * __expf(mo - nm);
            m[h] = nm;
        }
    }

    const int hl = lane >> 3;
    float mh  = (hl == 0) ? m[0] : (hl == 1) ? m[1] : (hl == 2) ? m[2] : m[3];
    float sh  = (hl == 0) ? s[0] : (hl == 1) ? s[1] : (hl == 2) ? s[2] : s[3];
    float inv = 1.f / fmaxf(sh, 1e-16f);
    float adl = (hl == 0) ? adh[0] : (hl == 1) ? adh[1] : (hl == 2) ? adh[2] : adh[3];

    // ---- pass 2: weighted aggregate; lane owns 4 contiguous channels
    float4 acc = make_float4(0.f, 0.f, 0.f, 0.f);
#pragma unroll 4
    for (int i = 0; i < deg; i++) {
        int src = g_csr_src[start + i];                 // broadcast load
        float asv = g_asrc[src * HEADS + hl];           // 1-sector broadcast
        float e = asv + adl;
        e = (e > 0.f) ? e : NEG_SLOPE * e;
        float alpha = __expf(e - mh) * inv;
        float4 hv = *(const float4*)&g_h[src * FOUT + lane4];  // 512B/warp, L2
        acc.x += alpha * hv.x;
        acc.y += alpha * hv.y;
        acc.z += alpha * hv.z;
        acc.w += alpha * hv.w;
    }
    acc.x += bv.x; acc.y += bv.y; acc.z += bv.z; acc.w += bv.w;
    *(float4*)&out[n * FOUT + lane4] = acc;
}

// ---------------- launch --------------------------------------------------
extern "C" void kernel_launch(void* const* d_in, const int* in_sizes, int n_in,
                              void* d_out, int out_size) {
    const float* x       = (const float*)d_in[0];
    const int*   edges   = (const int*)d_in[1];    // int32! (JAX x64 disabled)
    const float* W       = (const float*)d_in[2];
    const float* att_src = (const float*)d_in[3];
    const float* att_dst = (const float*)d_in[4];
    const float* bias    = (const float*)d_in[5];
    float*       out     = (float*)d_out;

    const int gemm_smem = GEMM_SMEM_U32 * 4;   // 96 KB
    cudaFuncSetAttribute(gemm_tf32_kernel,
                         cudaFuncAttributeMaxDynamicSharedMemorySize, gemm_smem);

    gemm_tf32_kernel<<<(NN + 63) / 64, 256, gemm_smem>>>(x, W);
    a_kernel<<<(NN * 32 + 255) / 256, 256>>>(att_src, att_dst);
    zero_deg_kernel<<<(NN + 255) / 256, 256>>>();
    hist_kernel<<<(EE + 255) / 256, 256>>>(edges);
    scan_kernel<<<1, 1024>>>();
    scatter_kernel<<<(EE + 255) / 256, 256>>>(edges);
    gat_kernel<<<(NN * 32 + 255) / 256, 256>>>(bias, out);
}

// round 4
// speedup vs baseline: 1.3167x; 1.3167x over previous
#include <cuda_runtime.h>
#include <cuda_bf16.h>
#include <math.h>

#define NN 50000
#define EE 800000
#define FIN 128
#define FOUT 128   // HEADS*C_OUT
#define HEADS 4
#define COUT 32
#define NEG_SLOPE 0.2f

// ---------------- scratch (device globals; no allocation) ----------------
__device__ __align__(16) float g_h[NN * FOUT];      // projected features
__device__ __align__(16) float g_asrc[NN * HEADS];  // per-node src logits
__device__ __align__(16) float g_adst[NN * HEADS];  // per-node dst logits
__device__ __align__(16) unsigned g_Wf[FIN * FOUT]; // permuted tf32 W fragments (64KB)
__device__ int g_deg[NN];
__device__ int g_off[NN];
__device__ int g_cur[NN];
__device__ int g_csr_src[EE];

// ---------------- tf32 helpers -------------------------------------------
__device__ __forceinline__ unsigned tf32_of(float f) {
    unsigned u;
    asm("cvt.rna.tf32.f32 %0, %1;" : "=r"(u) : "f"(f));
    return u;
}

__device__ __forceinline__ void mma_tf32(float* d, const unsigned* a, const unsigned* b) {
    asm("mma.sync.aligned.m16n8k8.row.col.f32.tf32.tf32.f32 "
        "{%0,%1,%2,%3},{%4,%5,%6,%7},{%8,%9},{%0,%1,%2,%3};"
        : "+f"(d[0]), "+f"(d[1]), "+f"(d[2]), "+f"(d[3])
        : "r"(a[0]), "r"(a[1]), "r"(a[2]), "r"(a[3]), "r"(b[0]), "r"(b[1]));
}

// ---------------- one-time W fragment permute ----------------------------
// B tile (ki,ni) k8n8: elem(kk,nn) -> lane=nn*4+(kk&3), reg=kk>>2
__global__ void wperm_kernel(const float* __restrict__ W) {
    int i = blockIdx.x * blockDim.x + threadIdx.x;   // 16384 elems
    if (i >= FIN * FOUT) return;
    int k = i >> 7, n = i & 127;
    int ki = k >> 3, kk = k & 7;
    int ni = n >> 3, nn = n & 7;
    int ln = nn * 4 + (kk & 3);
    int rg = kk >> 2;
    g_Wf[(ki * 16 + ni) * 64 + ln * 2 + rg] = tf32_of(W[k * FOUT + n]);
}

// ---------------- GEMM: h = x @ W  (tf32 tensor cores) --------------------
// Block: 128 rows x 128 cols, 256 threads (8 warps).
// A: natural row-major fp32 in smem, row stride 132 (conflict-free frag reads)
// B: vectorized copy of pre-permuted g_Wf
#define A_STRIDE 132
#define GEMM_SMEM_BYTES (128 * A_STRIDE * 4 + FIN * FOUT * 4)   // 66KB + 64KB

__global__ void __launch_bounds__(256, 1) gemm_tf32_kernel(const float* __restrict__ x) {
    extern __shared__ __align__(16) float smem_f[];
    float* sX = smem_f;                                   // 128 x 132
    unsigned* sB = (unsigned*)(smem_f + 128 * A_STRIDE);  // 16 ki x 16 ni x 64

    const int tid = threadIdx.x;
    const int rowBase = blockIdx.x * 128;

    // ---- stage A: coalesced float4, natural layout
#pragma unroll
    for (int j = 0; j < 16; j++) {
        int idx4 = tid + j * 256;          // 0..4095
        int r = idx4 >> 5;
        int c0 = (idx4 & 31) * 4;
        int gr = rowBase + r;
        float4 v = (gr < NN) ? *(const float4*)&x[gr * FIN + c0]
                             : make_float4(0.f, 0.f, 0.f, 0.f);
        *(float4*)&sX[r * A_STRIDE + c0] = v;
    }
    // ---- stage B: straight uint4 copy of permuted fragments
#pragma unroll
    for (int j = 0; j < 16; j++) {
        int idx4 = tid + j * 256;          // 0..4095
        ((uint4*)sB)[idx4] = ((const uint4*)g_Wf)[idx4];
    }
    __syncthreads();

    // ---- compute: warp owns 2 m-tiles x 8 n-tiles
    const int wid = tid >> 5, lane = tid & 31;
    const int mi0 = (wid & 3) * 2;
    const int nb  = (wid >> 2) * 8;
    const int lr  = lane >> 2;      // 0..7
    const int lc  = lane & 3;       // 0..3

    float acc[2][8][4];
#pragma unroll
    for (int t = 0; t < 2; t++)
#pragma unroll
        for (int nj = 0; nj < 8; nj++)
#pragma unroll
            for (int c = 0; c < 4; c++) acc[t][nj][c] = 0.f;

#pragma unroll 4
    for (int ki = 0; ki < 16; ki++) {
        int c = ki * 8 + lc;
        unsigned a[2][4];
#pragma unroll
        for (int t = 0; t < 2; t++) {
            int r = (mi0 + t) * 16 + lr;
            a[t][0] = tf32_of(sX[r * A_STRIDE + c]);
            a[t][1] = tf32_of(sX[(r + 8) * A_STRIDE + c]);
            a[t][2] = tf32_of(sX[r * A_STRIDE + c + 4]);
            a[t][3] = tf32_of(sX[(r + 8) * A_STRIDE + c + 4]);
        }
#pragma unroll
        for (int nj = 0; nj < 8; nj++) {
            uint2 b2 = *(const uint2*)&sB[(ki * 16 + nb + nj) * 64 + lane * 2];
            unsigned b[2] = {b2.x, b2.y};
            mma_tf32(acc[0][nj], a[0], b);
            mma_tf32(acc[1][nj], a[1], b);
        }
    }

    // ---- epilogue
#pragma unroll
    for (int t = 0; t < 2; t++) {
        int r0 = rowBase + (mi0 + t) * 16 + lr;
        int r1 = r0 + 8;
#pragma unroll
        for (int nj = 0; nj < 8; nj++) {
            int col0 = (nb + nj) * 8 + lc * 2;
            if (r0 < NN) *(float2*)&g_h[r0 * FOUT + col0] = make_float2(acc[t][nj][0], acc[t][nj][1]);
            if (r1 < NN) *(float2*)&g_h[r1 * FOUT + col0] = make_float2(acc[t][nj][2], acc[t][nj][3]);
        }
    }
}

// ---------------- per-node attention logits (warp per node) --------------
__global__ void a_kernel(const float* __restrict__ att_src, const float* __restrict__ att_dst) {
    int warp = (blockIdx.x * blockDim.x + threadIdx.x) >> 5;
    int lane = threadIdx.x & 31;
    if (warp >= NN) return;

    float4 hv = *(const float4*)&g_h[warp * FOUT + lane * 4];
    int head = lane >> 3;
    int off  = (lane & 7) * 4;
    const float* as = att_src + head * COUT + off;
    const float* ad = att_dst + head * COUT + off;
    float ps = hv.x * as[0] + hv.y * as[1] + hv.z * as[2] + hv.w * as[3];
    float pd = hv.x * ad[0] + hv.y * ad[1] + hv.z * ad[2] + hv.w * ad[3];
#pragma unroll
    for (int d = 4; d >= 1; d >>= 1) {
        ps += __shfl_xor_sync(0xffffffffu, ps, d);
        pd += __shfl_xor_sync(0xffffffffu, pd, d);
    }
    if ((lane & 7) == 0) {
        g_asrc[warp * HEADS + head] = ps;
        g_adst[warp * HEADS + head] = pd;
    }
}

// ---------------- CSR build ----------------------------------------------
__global__ void zero_deg_kernel() {
    int i = blockIdx.x * blockDim.x + threadIdx.x;
    if (i < NN) g_deg[i] = 0;
}

// edges are INT32 (JAX x64 disabled). layout: edges[0:EE]=src, edges[EE:2EE]=dst
__global__ void hist_kernel(const int* __restrict__ edges) {
    int t = blockIdx.x * blockDim.x + threadIdx.x;
    if (t < EE / 4) {
        int4 d = ((const int4*)(edges + EE))[t];
        atomicAdd(&g_deg[d.x], 1);
        atomicAdd(&g_deg[d.y], 1);
        atomicAdd(&g_deg[d.z], 1);
        atomicAdd(&g_deg[d.w], 1);
    }
}

__global__ void scan_kernel() {   // 1 block, 1024 threads, exclusive scan of g_deg
    __shared__ int ssum[1024];
    const int CH = (NN + 1023) / 1024;   // 49
    int t = threadIdx.x;
    int base = t * CH;

    int s = 0;
    for (int i = 0; i < CH; i++) {
        int idx = base + i;
        if (idx < NN) s += g_deg[idx];
    }
    ssum[t] = s;
    __syncthreads();
    for (int d = 1; d < 1024; d <<= 1) {
        int v = 0;
        if (t >= d) v = ssum[t - d];
        __syncthreads();
        ssum[t] += v;
        __syncthreads();
    }
    int prefix = (t > 0) ? ssum[t - 1] : 0;
    for (int i = 0; i < CH; i++) {
        int idx = base + i;
        if (idx < NN) {
            g_off[idx] = prefix;
            g_cur[idx] = prefix;
            prefix += g_deg[idx];
        }
    }
}

__global__ void scatter_kernel(const int* __restrict__ edges) {
    int t = blockIdx.x * blockDim.x + threadIdx.x;
    if (t < EE / 4) {
        int4 s4 = ((const int4*)edges)[t];
        int4 d4 = ((const int4*)(edges + EE))[t];
        g_csr_src[atomicAdd(&g_cur[d4.x], 1)] = s4.x;
        g_csr_src[atomicAdd(&g_cur[d4.y], 1)] = s4.y;
        g_csr_src[atomicAdd(&g_cur[d4.z], 1)] = s4.z;
        g_csr_src[atomicAdd(&g_cur[d4.w], 1)] = s4.w;
    }
}

// ---------------- GAT aggregate: warp per dst node -----------------------
__global__ void gat_kernel(const float* __restrict__ bias, float* __restrict__ out) {
    int warp = (blockIdx.x * blockDim.x + threadIdx.x) >> 5;
    int lane = threadIdx.x & 31;
    if (warp >= NN) return;
    const int n = warp;

    const int start = g_off[n];
    const int deg   = g_deg[n];
    const int lane4 = lane * 4;
    float4 bv = *(const float4*)&bias[lane4];

    if (deg == 0) {
        *(float4*)&out[n * FOUT + lane4] = bv;
        return;
    }

    float4 ad4 = *(const float4*)&g_adst[n * HEADS];
    float adh[4] = {ad4.x, ad4.y, ad4.z, ad4.w};

    // ---- pass 1: online softmax stats per head, lane-parallel over edges
    float m[4] = {-1e30f, -1e30f, -1e30f, -1e30f};
    float s[4] = {0.f, 0.f, 0.f, 0.f};
    for (int i = lane; i < deg; i += 32) {
        int src = g_csr_src[start + i];
        float4 as4 = *(const float4*)&g_asrc[src * HEADS];
        float ev[4] = {as4.x + adh[0], as4.y + adh[1], as4.z + adh[2], as4.w + adh[3]};
#pragma unroll
        for (int h = 0; h < 4; h++) {
            float e = ev[h];
            e = (e > 0.f) ? e : NEG_SLOPE * e;
            float nm = fmaxf(m[h], e);
            s[h] = s[h] * __expf(m[h] - nm) + __expf(e - nm);
            m[h] = nm;
        }
    }
    // warp combine (safe with -1e30 sentinel: no inf-inf NaN)
#pragma unroll
    for (int h = 0; h < 4; h++) {
#pragma unroll
        for (int d = 16; d >= 1; d >>= 1) {
            float mo = __shfl_xor_sync(0xffffffffu, m[h], d);
            float so = __shfl_xor_sync(0xffffffffu, s[h], d);
            float nm = fmaxf(m[h], mo);
            s[h] = s[h] * __expf(m[h] - nm) + so * __expf(mo - nm);
            m[h] = nm;
        }
    }

    const int hl = lane >> 3;
    float mh  = (hl == 0) ? m[0] : (hl == 1) ? m[1] : (hl == 2) ? m[2] : m[3];
    float sh  = (hl == 0) ? s[0] : (hl == 1) ? s[1] : (hl == 2) ? s[2] : s[3];
    float inv = 1.f / fmaxf(sh, 1e-16f);
    float adl = (hl == 0) ? adh[0] : (hl == 1) ? adh[1] : (hl == 2) ? adh[2] : adh[3];

    // ---- pass 2: weighted aggregate; lane owns 4 contiguous channels
    float4 acc = make_float4(0.f, 0.f, 0.f, 0.f);
#pragma unroll 4
    for (int i = 0; i < deg; i++) {
        int src = g_csr_src[start + i];                 // broadcast load
        float asv = g_asrc[src * HEADS + hl];           // 1-sector broadcast
        float e = asv + adl;
        e = (e > 0.f) ? e : NEG_SLOPE * e;
        float alpha = __expf(e - mh) * inv;
        float4 hv = *(const float4*)&g_h[src * FOUT + lane4];  // 512B/warp, L2
        acc.x += alpha * hv.x;
        acc.y += alpha * hv.y;
        acc.z += alpha * hv.z;
        acc.w += alpha * hv.w;
    }
    acc.x += bv.x; acc.y += bv.y; acc.z += bv.z; acc.w += bv.w;
    *(float4*)&out[n * FOUT + lane4] = acc;
}

// ---------------- launch --------------------------------------------------
extern "C" void kernel_launch(void* const* d_in, const int* in_sizes, int n_in,
                              void* d_out, int out_size) {
    const float* x       = (const float*)d_in[0];
    const int*   edges   = (const int*)d_in[1];    // int32! (JAX x64 disabled)
    const float* W       = (const float*)d_in[2];
    const float* att_src = (const float*)d_in[3];
    const float* att_dst = (const float*)d_in[4];
    const float* bias    = (const float*)d_in[5];
    float*       out     = (float*)d_out;

    cudaFuncSetAttribute(gemm_tf32_kernel,
                         cudaFuncAttributeMaxDynamicSharedMemorySize, GEMM_SMEM_BYTES);

    wperm_kernel<<<(FIN * FOUT + 255) / 256, 256>>>(W);
    gemm_tf32_kernel<<<(NN + 127) / 128, 256, GEMM_SMEM_BYTES>>>(x);
    a_kernel<<<(NN * 32 + 255) / 256, 256>>>(att_src, att_dst);
    zero_deg_kernel<<<(NN + 255) / 256, 256>>>();
    hist_kernel<<<(EE / 4 + 255) / 256, 256>>>(edges);
    scan_kernel<<<1, 1024>>>();
    scatter_kernel<<<(EE / 4 + 255) / 256, 256>>>(edges);
    gat_kernel<<<(NN * 32 + 255) / 256, 256>>>(bias, out);
}